// round 12
// baseline (speedup 1.0000x reference)
#include <cuda_runtime.h>
#include <cuda_fp16.h>
#include <math.h>

#define BB   128
#define SS   512
#define DD   512
#define TT   64
#define OUTD 3
#define GG   (3*DD)        // 1536

typedef unsigned long long u64;

// ---------------- scratch (device globals: allocation-free) ----------------
__device__ __half g_Uk [(size_t)BB*SS*DD];  // tanh(Ua(keys)+bu), fp16
__device__ __half g_e16[(size_t)BB*SS*DD];  // fp16 copy of e_all
__device__ float g_h   [BB*DD];             // decoder hidden state
__device__ float g_ctx [BB*DD];             // attention context
__device__ float g_qp  [4*BB*DD];           // split-K partials of q
__device__ float g_gip [4*BB*GG];           // split-K partials of gi
__device__ float g_ghp [4*BB*GG];           // split-K partials of gh
__device__ float g_W512[GG*DD];             // W_ih[:, :512] packed (aligned)
__device__ float g_Wx  [3*GG];              // W_ih[:, 512+j] packed [j][n]

// transcendentals (outside the hot loop)
__device__ __forceinline__ float tanh_fast(float x) {
    return 1.f - __fdividef(2.f, __expf(2.f*x) + 1.f);
}
__device__ __forceinline__ float sigmoid_fast(float x) {
    return __fdividef(1.f, 1.f + __expf(-x));
}

// ---- packed fp32x2 FMA helpers ----
__device__ __forceinline__ u64 bcast2(float x) {
    u64 d; asm("mov.b64 %0, {%1, %1};" : "=l"(d) : "f"(x)); return d;
}
__device__ __forceinline__ void ffma2(u64& acc, u64 a, u64 b) {
    asm("fma.rn.f32x2 %0, %1, %2, %0;" : "+l"(acc) : "l"(a), "l"(b));
}
__device__ __forceinline__ float2 unpack2(u64 v) {
    float2 f; asm("mov.b64 {%0, %1}, %2;" : "=f"(f.x), "=f"(f.y) : "l"(v)); return f;
}

// MUFU-free reciprocal for y in (0,2]: bit-hack seed + 2 Newton steps
__device__ __forceinline__ float rcp_fma(float y) {
    float r = __uint_as_float(0x7EF311C3u - __float_as_uint(y));
    r = r * fmaf(-y, r, 2.0f);
    r = r * fmaf(-y, r, 2.0f);
    return r;
}

// va * tanh(q+u) via tanh addition formula; tu=tanh(u), tq=tanh(q). No MUFU.
__device__ __forceinline__ float attn_term(float tu, float tq, float va) {
    float y = fmaf(tq, tu, 1.0f);
    return va * ((tq + tu) * rcp_fma(y));
}

// ---------------- prep: h0 = e_last; pack W_ih ----------------------------
__global__ void prep_kernel(const float* __restrict__ W_ih,
                            const float* __restrict__ e_last) {
    int i = blockIdx.x * blockDim.x + threadIdx.x;
    if (i < GG*DD) {
        int n = i >> 9, k = i & 511;
        g_W512[i] = W_ih[(size_t)n*515 + k];
    }
    int j = i - GG*DD;
    if (j >= 0 && j < BB*DD) g_h[j] = e_last[j];
    int m = i - GG*DD - BB*DD;
    if (m >= 0 && m < 3*GG) {
        int jj = m / GG, n = m % GG;
        g_Wx[m] = W_ih[(size_t)n*515 + 512 + jj];
    }
}

// ---------------- cvt: e16 = fp16(e_all) -----------------------------------
__global__ void cvt_kernel(const float* __restrict__ e_all) {
    size_t i = (size_t)blockIdx.x * blockDim.x + threadIdx.x;   // float4 index
    float4 v = ((const float4*)e_all)[i];
    __half2* o = (__half2*)g_e16 + i*2;
    o[0] = __floats2half2_rn(v.x, v.y);
    o[1] = __floats2half2_rn(v.z, v.w);
}

// ---------------- Uk GEMM -> tanh -> fp16 ---------------------------------
// M=65536, N=512, K=512. BM=128, BN=64, BK=16, 256 threads, f32x2 accum.
__global__ __launch_bounds__(256) void uk_gemm(const float* __restrict__ A,
                                               const float* __restrict__ W,
                                               const float* __restrict__ bias) {
    __shared__ __align__(16) float Xs[16][128];
    __shared__ __align__(16) float Ws[16][64];
    const int tid = threadIdx.x;
    const int tx = tid & 15, ty = tid >> 4;
    const int row0 = blockIdx.y * 128;
    const int n0   = blockIdx.x * 64;

    u64 acc2[4][4];
#pragma unroll
    for (int i = 0; i < 4; i++)
#pragma unroll
        for (int j = 0; j < 4; j++) acc2[i][j] = 0ull;

    for (int kc = 0; kc < 512; kc += 16) {
#pragma unroll
        for (int i = 0; i < 2; i++) {
            int l4 = tid*2 + i;
            int r = l4 >> 2, kq = (l4 & 3) << 2;
            float4 v = *(const float4*)(A + (size_t)(row0 + r)*512 + kc + kq);
            Xs[kq+0][r] = v.x; Xs[kq+1][r] = v.y; Xs[kq+2][r] = v.z; Xs[kq+3][r] = v.w;
        }
        {
            int n = tid >> 2, kq = (tid & 3) << 2;
            float4 v = *(const float4*)(W + (size_t)(n0 + n)*512 + kc + kq);
            Ws[kq+0][n] = v.x; Ws[kq+1][n] = v.y; Ws[kq+2][n] = v.z; Ws[kq+3][n] = v.w;
        }
        __syncthreads();
#pragma unroll
        for (int kk = 0; kk < 16; kk++) {
            const u64* ap = (const u64*)&Xs[kk][ty*8];
            u64 a2[4], b2[4];
#pragma unroll
            for (int i = 0; i < 4; i++) a2[i] = ap[i];
#pragma unroll
            for (int j = 0; j < 4; j++) b2[j] = bcast2(Ws[kk][tx*4 + j]);
#pragma unroll
            for (int i = 0; i < 4; i++)
#pragma unroll
                for (int j = 0; j < 4; j++) ffma2(acc2[i][j], a2[i], b2[j]);
        }
        __syncthreads();
    }
#pragma unroll
    for (int i = 0; i < 4; i++) {
        size_t r0r = (size_t)(row0 + ty*8 + 2*i);
#pragma unroll
        for (int j = 0; j < 4; j++) {
            int n = n0 + tx*4 + j;
            float2 v = unpack2(acc2[i][j]);
            g_Uk[r0r*512 + n]     = __float2half_rn(tanh_fast(v.x + bias[n]));
            g_Uk[(r0r+1)*512 + n] = __float2half_rn(tanh_fast(v.y + bias[n]));
        }
    }
}

// ---------------- skinny GEMM, K=512, split-K=4 ---------------------------
// which==0: bx<8 -> q (X=g_h, W=Wa, N=512); bx>=8 -> gh (X=g_h, W=Whh, N=1536)
// which==1: gi (X=g_ctx, W=g_W512, N=1536)
__global__ __launch_bounds__(256) void sk_gemm(const float* __restrict__ Wq,
                                               const float* __restrict__ Whh,
                                               int which) {
    __shared__ __align__(16) float Xs[16][128];
    __shared__ __align__(16) float Ws[16][64];
    const int tid = threadIdx.x;
    const int tx = tid & 15, ty = tid >> 4;
    const int bx = blockIdx.x;
    const int part = blockIdx.y;
    const float *X, *W; float* Cp; int n0, N;
    if (which == 0) {
        if (bx < 8) { X = g_h; W = Wq;  Cp = g_qp;  n0 = bx*64;     N = 512;  }
        else        { X = g_h; W = Whh; Cp = g_ghp; n0 = (bx-8)*64; N = 1536; }
    } else          { X = g_ctx; W = g_W512; Cp = g_gip; n0 = bx*64; N = 1536; }
    const int kb = part * 128;

    u64 acc2[4][4];
#pragma unroll
    for (int i = 0; i < 4; i++)
#pragma unroll
        for (int j = 0; j < 4; j++) acc2[i][j] = 0ull;

    for (int kc = kb; kc < kb + 128; kc += 16) {
#pragma unroll
        for (int i = 0; i < 2; i++) {
            int l4 = tid*2 + i;
            int r = l4 >> 2, kq = (l4 & 3) << 2;
            float4 v = *(const float4*)(X + (size_t)r*512 + kc + kq);
            Xs[kq+0][r] = v.x; Xs[kq+1][r] = v.y; Xs[kq+2][r] = v.z; Xs[kq+3][r] = v.w;
        }
        {
            int n = tid >> 2, kq = (tid & 3) << 2;
            float4 v = *(const float4*)(W + (size_t)(n0 + n)*512 + kc + kq);
            Ws[kq+0][n] = v.x; Ws[kq+1][n] = v.y; Ws[kq+2][n] = v.z; Ws[kq+3][n] = v.w;
        }
        __syncthreads();
#pragma unroll
        for (int kk = 0; kk < 16; kk++) {
            const u64* ap = (const u64*)&Xs[kk][ty*8];
            u64 a2[4], b2[4];
#pragma unroll
            for (int i = 0; i < 4; i++) a2[i] = ap[i];
#pragma unroll
            for (int j = 0; j < 4; j++) b2[j] = bcast2(Ws[kk][tx*4 + j]);
#pragma unroll
            for (int i = 0; i < 4; i++)
#pragma unroll
                for (int j = 0; j < 4; j++) ffma2(acc2[i][j], a2[i], b2[j]);
        }
        __syncthreads();
    }
#pragma unroll
    for (int i = 0; i < 4; i++) {
        int b0 = ty*8 + 2*i;
        size_t base0 = ((size_t)part*BB + b0)     * (size_t)N + n0;
        size_t base1 = ((size_t)part*BB + b0 + 1) * (size_t)N + n0;
#pragma unroll
        for (int j = 0; j < 4; j++) {
            float2 v = unpack2(acc2[i][j]);
            Cp[base0 + tx*4 + j] = v.x;
            Cp[base1 + tx*4 + j] = v.y;
        }
    }
}

// ---------------- attention (1024 threads, one block per b) ---------------
__global__ __launch_bounds__(1024) void attn_kernel(const float* __restrict__ ba,
                                                    const float* __restrict__ va,
                                                    const float* __restrict__ va_b,
                                                    float* __restrict__ out, int t) {
    const int b = blockIdx.x;
    const int tid = threadIdx.x;
    const int warp = tid >> 5, lane = tid & 31;
    __shared__ __align__(16) float tq_s[DD];
    __shared__ __align__(16) float w_s[SS];
    __shared__ float red[16];
    __shared__ float bval;
    __shared__ __align__(16) float2 part[4][256];

    if (tid < DD) {
        int off = b*DD + tid;
        float qv = ba[tid] + g_qp[off] + g_qp[BB*DD + off]
                 + g_qp[2*BB*DD + off] + g_qp[3*BB*DD + off];
        tq_s[tid] = tanh_fast(qv);
    }
    __syncthreads();

    // this lane's 16 d-values: [lane*16, lane*16+16)
    float tqv[16], vav[16];
#pragma unroll
    for (int k = 0; k < 4; k++) {
        float4 a = *(const float4*)(tq_s + lane*16 + k*4);
        float4 c = *(const float4*)(va   + lane*16 + k*4);
        tqv[k*4+0]=a.x; tqv[k*4+1]=a.y; tqv[k*4+2]=a.z; tqv[k*4+3]=a.w;
        vav[k*4+0]=c.x; vav[k*4+1]=c.y; vav[k*4+2]=c.z; vav[k*4+3]=c.w;
    }
    const float vb = va_b[0];

    // pass 1: scores. warp per s, 32 warps stride S; Uk already tanh'ed (fp16)
#pragma unroll 1
    for (int s = warp; s < SS; s += 32) {
        const __half* u = g_Uk + ((size_t)b*SS + s)*DD + lane*16;
        uint4 A0 = *(const uint4*)u;
        uint4 A1 = *(const uint4*)(u + 8);
        const __half2* h0 = (const __half2*)&A0;
        const __half2* h1 = (const __half2*)&A1;
        float acc = 0.f;
#pragma unroll
        for (int j = 0; j < 4; j++) {
            float2 f = __half22float2(h0[j]);
            acc += attn_term(f.x, tqv[j*2+0], vav[j*2+0]);
            acc += attn_term(f.y, tqv[j*2+1], vav[j*2+1]);
        }
#pragma unroll
        for (int j = 0; j < 4; j++) {
            float2 f = __half22float2(h1[j]);
            acc += attn_term(f.x, tqv[8+j*2+0], vav[8+j*2+0]);
            acc += attn_term(f.y, tqv[8+j*2+1], vav[8+j*2+1]);
        }
#pragma unroll
        for (int o = 16; o > 0; o >>= 1) acc += __shfl_xor_sync(0xffffffffu, acc, o);
        if (lane == 0) w_s[s] = acc + vb;
    }
    __syncthreads();

    // softmax over S (threads 0..511)
    float sc = 0.f, ex = 0.f;
    if (tid < SS) {
        sc = w_s[tid];
        float m = sc;
#pragma unroll
        for (int o = 16; o > 0; o >>= 1) m = fmaxf(m, __shfl_xor_sync(0xffffffffu, m, o));
        if (lane == 0) red[warp] = m;
    }
    __syncthreads();
    if (tid == 0) {
        float mm = red[0];
#pragma unroll
        for (int i = 1; i < 16; i++) mm = fmaxf(mm, red[i]);
        bval = mm;
    }
    __syncthreads();
    if (tid < SS) {
        ex = __expf(sc - bval);
        float sm = ex;
#pragma unroll
        for (int o = 16; o > 0; o >>= 1) sm += __shfl_xor_sync(0xffffffffu, sm, o);
        if (lane == 0) red[warp] = sm;
    }
    __syncthreads();
    if (tid == 0) {
        float tt = 0.f;
#pragma unroll
        for (int i = 0; i < 16; i++) tt += red[i];
        bval = tt;
    }
    __syncthreads();
    if (tid < SS) {
        float wv = __fdividef(ex, bval);
        w_s[tid] = wv;
        out[(size_t)(BB*TT*OUTD + BB*DD) + ((size_t)b*TT + t)*SS + tid] = wv;
    }
    __syncthreads();

    // pass 2: ctx. 4 groups of 256 threads; group g covers s in [g*128,g*128+128)
    {
        const int g = tid >> 8, l = tid & 255;
        const __half2* ep = (const __half2*)(g_e16 + ((size_t)b*SS + g*128)*DD) + l;
        float2 acc = make_float2(0.f, 0.f);
#pragma unroll 4
        for (int s = 0; s < 128; s++) {
            float wv = w_s[g*128 + s];
            float2 f = __half22float2(ep[(size_t)s * 256]);
            acc.x = fmaf(wv, f.x, acc.x);
            acc.y = fmaf(wv, f.y, acc.y);
        }
        part[g][l] = acc;
    }
    __syncthreads();
    if (tid < 256) {
        float2 a = part[0][tid], b2 = part[1][tid], c = part[2][tid], d2 = part[3][tid];
        float2 r;
        r.x = (a.x + b2.x) + (c.x + d2.x);
        r.y = (a.y + b2.y) + (c.y + d2.y);
        ((float2*)(g_ctx + b*DD))[tid] = r;
    }
}

// ---------------- GRU pointwise + x-term + output projection --------------
__global__ __launch_bounds__(512) void point_kernel(const float* __restrict__ b_ih,
                                                    const float* __restrict__ b_hh,
                                                    const float* __restrict__ W_out,
                                                    const float* __restrict__ b_out,
                                                    const float* __restrict__ target,
                                                    float* __restrict__ out, int t) {
    const int b = blockIdx.x, d = threadIdx.x;
    const int base = b*DD + d;

    float ir = b_ih[d], iz = b_ih[DD+d], in_ = b_ih[2*DD+d];
    float hr = b_hh[d], hz = b_hh[DD+d], hn  = b_hh[2*DD+d];
#pragma unroll
    for (int p = 0; p < 4; p++) {
        size_t o = ((size_t)p*BB + b)*GG;
        ir += g_gip[o + d]; iz += g_gip[o + DD + d]; in_ += g_gip[o + 2*DD + d];
        hr += g_ghp[o + d]; hz += g_ghp[o + DD + d]; hn  += g_ghp[o + 2*DD + d];
    }
    // teacher-forced x contribution (rank-3)
    float x0 = 0.f, x1 = 0.f, x2 = 0.f;
    if (t > 0) {
        const float* xp = target + ((size_t)b*TT + (t-1))*OUTD;
        x0 = xp[0]; x1 = xp[1]; x2 = xp[2];
    }
    ir  += x0*g_Wx[d]        + x1*g_Wx[GG + d]        + x2*g_Wx[2*GG + d];
    iz  += x0*g_Wx[DD+d]     + x1*g_Wx[GG + DD+d]     + x2*g_Wx[2*GG + DD+d];
    in_ += x0*g_Wx[2*DD+d]   + x1*g_Wx[GG + 2*DD+d]   + x2*g_Wx[2*GG + 2*DD+d];

    float r = sigmoid_fast(ir + hr);
    float z = sigmoid_fast(iz + hz);
    float n = tanh_fast(in_ + r*hn);
    float hp = g_h[base];
    float hnew = (1.f - z)*n + z*hp;
    g_h[base] = hnew;
    if (t == TT-1) out[BB*TT*OUTD + base] = hnew;   // hT region

    // out = h_new @ W_out^T + b_out
    float p0 = hnew*W_out[d], p1 = hnew*W_out[DD+d], p2 = hnew*W_out[2*DD+d];
#pragma unroll
    for (int o = 16; o > 0; o >>= 1) {
        p0 += __shfl_xor_sync(0xffffffffu, p0, o);
        p1 += __shfl_xor_sync(0xffffffffu, p1, o);
        p2 += __shfl_xor_sync(0xffffffffu, p2, o);
    }
    __shared__ float r0[16], r1[16], r2[16];
    int warp = d >> 5, lane = d & 31;
    if (lane == 0) { r0[warp] = p0; r1[warp] = p1; r2[warp] = p2; }
    __syncthreads();
    if (d == 0) {
        float s0=0.f, s1=0.f, s2=0.f;
#pragma unroll
        for (int i = 0; i < 16; i++) { s0 += r0[i]; s1 += r1[i]; s2 += r2[i]; }
        size_t ob = ((size_t)b*TT + t)*OUTD;
        out[ob+0] = s0 + b_out[0];
        out[ob+1] = s1 + b_out[1];
        out[ob+2] = s2 + b_out[2];
    }
}

// ---------------- host launcher -------------------------------------------
extern "C" void kernel_launch(void* const* d_in, const int* in_sizes, int n_in,
                              void* d_out, int out_size) {
    (void)in_sizes; (void)n_in; (void)out_size;
    const float* e_all  = (const float*)d_in[0];
    const float* e_last = (const float*)d_in[1];
    const float* target = (const float*)d_in[2];
    const float* Wa     = (const float*)d_in[3];
    const float* ba     = (const float*)d_in[4];
    const float* Ua     = (const float*)d_in[5];
    const float* bu     = (const float*)d_in[6];
    const float* Va_w   = (const float*)d_in[7];
    const float* Va_b   = (const float*)d_in[8];
    const float* W_ih   = (const float*)d_in[9];
    const float* b_ih   = (const float*)d_in[10];
    const float* W_hh   = (const float*)d_in[11];
    const float* b_hh   = (const float*)d_in[12];
    const float* W_out  = (const float*)d_in[13];
    const float* b_out  = (const float*)d_in[14];
    float* out = (float*)d_out;

    prep_kernel<<<(GG*DD + BB*DD + 3*GG + 255)/256, 256>>>(W_ih, e_last);
    cvt_kernel<<<(BB*SS*DD/4)/1024, 1024>>>(e_all);
    uk_gemm<<<dim3(8, 512), 256>>>(e_all, Ua, bu);

    for (int t = 0; t < TT; t++) {
        sk_gemm<<<dim3(32, 4), 256>>>(Wa, W_hh, 0);                    // q + gh partials
        attn_kernel<<<BB, 1024>>>(ba, Va_w, Va_b, out, t);             // w, ctx
        sk_gemm<<<dim3(24, 4), 256>>>(Wa, W_hh, 1);                    // gi partials
        point_kernel<<<BB, 512>>>(b_ih, b_hh, W_out, b_out, target, out, t);
    }
}

// round 13
// speedup vs baseline: 1.2500x; 1.2500x over previous
#include <cuda_runtime.h>
#include <cuda_fp16.h>
#include <math.h>

#define BB   128
#define SS   512
#define DD   512
#define TT   64
#define OUTD 3
#define GG   (3*DD)        // 1536
#define NP   8             // split-K parts

typedef unsigned long long u64;

// ---------------- scratch (device globals: allocation-free) ----------------
__device__ __half g_Uk [(size_t)BB*SS*DD];  // tanh(Ua(keys)+bu), fp16
__device__ __half g_e16[(size_t)BB*SS*DD];  // fp16 copy of e_all
__device__ float g_h   [BB*DD];             // decoder hidden state
__device__ float g_ctx [BB*DD];             // attention context
__device__ float g_qp  [NP*BB*DD];          // split-K partials of q
__device__ float g_gip [NP*BB*GG];          // split-K partials of gi
__device__ float g_ghp [NP*BB*GG];          // split-K partials of gh
__device__ float g_W512[GG*DD];             // W_ih[:, :512] packed (aligned)
__device__ float g_Wx  [3*GG];              // W_ih[:, 512+j] packed [j][n]

// transcendentals (outside the hot loop)
__device__ __forceinline__ float tanh_fast(float x) {
    return 1.f - __fdividef(2.f, __expf(2.f*x) + 1.f);
}
__device__ __forceinline__ float sigmoid_fast(float x) {
    return __fdividef(1.f, 1.f + __expf(-x));
}

// ---- packed fp32x2 FMA helpers ----
__device__ __forceinline__ u64 bcast2(float x) {
    u64 d; asm("mov.b64 %0, {%1, %1};" : "=l"(d) : "f"(x)); return d;
}
__device__ __forceinline__ void ffma2(u64& acc, u64 a, u64 b) {
    asm("fma.rn.f32x2 %0, %1, %2, %0;" : "+l"(acc) : "l"(a), "l"(b));
}
__device__ __forceinline__ float2 unpack2(u64 v) {
    float2 f; asm("mov.b64 {%0, %1}, %2;" : "=f"(f.x), "=f"(f.y) : "l"(v)); return f;
}

// MUFU-free reciprocal for y in (0,2]: bit-hack seed + 2 Newton steps
__device__ __forceinline__ float rcp_fma(float y) {
    float r = __uint_as_float(0x7EF311C3u - __float_as_uint(y));
    r = r * fmaf(-y, r, 2.0f);
    r = r * fmaf(-y, r, 2.0f);
    return r;
}

// va * tanh(q+u) via tanh addition formula; tu=tanh(u), tq=tanh(q). No MUFU.
__device__ __forceinline__ float attn_term(float tu, float tq, float va) {
    float y = fmaf(tq, tu, 1.0f);
    return va * ((tq + tu) * rcp_fma(y));
}

// ---------------- prep: h0 = e_last; pack W_ih ----------------------------
__global__ void prep_kernel(const float* __restrict__ W_ih,
                            const float* __restrict__ e_last) {
    int i = blockIdx.x * blockDim.x + threadIdx.x;
    if (i < GG*DD) {
        int n = i >> 9, k = i & 511;
        g_W512[i] = W_ih[(size_t)n*515 + k];
    }
    int j = i - GG*DD;
    if (j >= 0 && j < BB*DD) g_h[j] = e_last[j];
    int m = i - GG*DD - BB*DD;
    if (m >= 0 && m < 3*GG) {
        int jj = m / GG, n = m % GG;
        g_Wx[m] = W_ih[(size_t)n*515 + 512 + jj];
    }
}

// ---------------- cvt: e16 = fp16(e_all) -----------------------------------
__global__ void cvt_kernel(const float* __restrict__ e_all) {
    size_t i = (size_t)blockIdx.x * blockDim.x + threadIdx.x;   // float4 index
    float4 v = ((const float4*)e_all)[i];
    __half2* o = (__half2*)g_e16 + i*2;
    o[0] = __floats2half2_rn(v.x, v.y);
    o[1] = __floats2half2_rn(v.z, v.w);
}

// ---------------- Uk GEMM -> tanh -> fp16 ---------------------------------
// M=65536, N=512, K=512. BM=128, BN=64, BK=16, 256 threads, f32x2 accum.
__global__ __launch_bounds__(256) void uk_gemm(const float* __restrict__ A,
                                               const float* __restrict__ W,
                                               const float* __restrict__ bias) {
    __shared__ __align__(16) float Xs[16][128];
    __shared__ __align__(16) float Ws[16][64];
    const int tid = threadIdx.x;
    const int tx = tid & 15, ty = tid >> 4;
    const int row0 = blockIdx.y * 128;
    const int n0   = blockIdx.x * 64;

    u64 acc2[4][4];
#pragma unroll
    for (int i = 0; i < 4; i++)
#pragma unroll
        for (int j = 0; j < 4; j++) acc2[i][j] = 0ull;

    for (int kc = 0; kc < 512; kc += 16) {
#pragma unroll
        for (int i = 0; i < 2; i++) {
            int l4 = tid*2 + i;
            int r = l4 >> 2, kq = (l4 & 3) << 2;
            float4 v = *(const float4*)(A + (size_t)(row0 + r)*512 + kc + kq);
            Xs[kq+0][r] = v.x; Xs[kq+1][r] = v.y; Xs[kq+2][r] = v.z; Xs[kq+3][r] = v.w;
        }
        {
            int n = tid >> 2, kq = (tid & 3) << 2;
            float4 v = *(const float4*)(W + (size_t)(n0 + n)*512 + kc + kq);
            Ws[kq+0][n] = v.x; Ws[kq+1][n] = v.y; Ws[kq+2][n] = v.z; Ws[kq+3][n] = v.w;
        }
        __syncthreads();
#pragma unroll
        for (int kk = 0; kk < 16; kk++) {
            const u64* ap = (const u64*)&Xs[kk][ty*8];
            u64 a2[4], b2[4];
#pragma unroll
            for (int i = 0; i < 4; i++) a2[i] = ap[i];
#pragma unroll
            for (int j = 0; j < 4; j++) b2[j] = bcast2(Ws[kk][tx*4 + j]);
#pragma unroll
            for (int i = 0; i < 4; i++)
#pragma unroll
                for (int j = 0; j < 4; j++) ffma2(acc2[i][j], a2[i], b2[j]);
        }
        __syncthreads();
    }
#pragma unroll
    for (int i = 0; i < 4; i++) {
        size_t r0r = (size_t)(row0 + ty*8 + 2*i);
#pragma unroll
        for (int j = 0; j < 4; j++) {
            int n = n0 + tx*4 + j;
            float2 v = unpack2(acc2[i][j]);
            g_Uk[r0r*512 + n]     = __float2half_rn(tanh_fast(v.x + bias[n]));
            g_Uk[(r0r+1)*512 + n] = __float2half_rn(tanh_fast(v.y + bias[n]));
        }
    }
}

// ---------------- skinny GEMM, K=512, split-K=8 (template: no runtime sel) -
// WHICH==0: bx<8 -> q (X=g_h, W=Wa, N=512); bx>=8 -> gh (X=g_h, W=Whh, N=1536)
// WHICH==1: gi (X=g_ctx, W=g_W512, N=1536)
template<int WHICH>
__global__ __launch_bounds__(256) void sk_gemm(const float* __restrict__ Wq,
                                               const float* __restrict__ Whh) {
    __shared__ __align__(16) float Xs[16][128];
    __shared__ __align__(16) float Ws[16][64];
    const int tid = threadIdx.x;
    const int tx = tid & 15, ty = tid >> 4;
    const int bx = blockIdx.x;
    const int part = blockIdx.y;
    const float *X, *W; float* Cp; int n0, N;
    if (WHICH == 0) {
        if (bx < 8) { X = g_h; W = Wq;  Cp = g_qp;  n0 = bx*64;     N = 512;  }
        else        { X = g_h; W = Whh; Cp = g_ghp; n0 = (bx-8)*64; N = 1536; }
    } else          { X = g_ctx; W = g_W512; Cp = g_gip; n0 = bx*64; N = 1536; }
    const int kb = part * 64;

    u64 acc2[4][4];
#pragma unroll
    for (int i = 0; i < 4; i++)
#pragma unroll
        for (int j = 0; j < 4; j++) acc2[i][j] = 0ull;

#pragma unroll
    for (int kc = kb; kc < kb + 64; kc += 16) {
#pragma unroll
        for (int i = 0; i < 2; i++) {
            int l4 = tid*2 + i;
            int r = l4 >> 2, kq = (l4 & 3) << 2;
            float4 v = *(const float4*)(X + (size_t)r*512 + kc + kq);
            Xs[kq+0][r] = v.x; Xs[kq+1][r] = v.y; Xs[kq+2][r] = v.z; Xs[kq+3][r] = v.w;
        }
        {
            int n = tid >> 2, kq = (tid & 3) << 2;
            float4 v = *(const float4*)(W + (size_t)(n0 + n)*512 + kc + kq);
            Ws[kq+0][n] = v.x; Ws[kq+1][n] = v.y; Ws[kq+2][n] = v.z; Ws[kq+3][n] = v.w;
        }
        __syncthreads();
#pragma unroll
        for (int kk = 0; kk < 16; kk++) {
            const u64* ap = (const u64*)&Xs[kk][ty*8];
            u64 a2[4], b2[4];
#pragma unroll
            for (int i = 0; i < 4; i++) a2[i] = ap[i];
#pragma unroll
            for (int j = 0; j < 4; j++) b2[j] = bcast2(Ws[kk][tx*4 + j]);
#pragma unroll
            for (int i = 0; i < 4; i++)
#pragma unroll
                for (int j = 0; j < 4; j++) ffma2(acc2[i][j], a2[i], b2[j]);
        }
        __syncthreads();
    }
#pragma unroll
    for (int i = 0; i < 4; i++) {
        int b0 = ty*8 + 2*i;
        size_t base0 = ((size_t)part*BB + b0)     * (size_t)N + n0;
        size_t base1 = ((size_t)part*BB + b0 + 1) * (size_t)N + n0;
#pragma unroll
        for (int j = 0; j < 4; j++) {
            float2 v = unpack2(acc2[i][j]);
            Cp[base0 + tx*4 + j] = v.x;
            Cp[base1 + tx*4 + j] = v.y;
        }
    }
}

// ---------------- attention (512 threads, one block per b) ----------------
__global__ __launch_bounds__(512) void attn_kernel(const float* __restrict__ ba,
                                                   const float* __restrict__ va,
                                                   const float* __restrict__ va_b,
                                                   float* __restrict__ out, int t) {
    const int b = blockIdx.x;
    const int tid = threadIdx.x;
    const int warp = tid >> 5, lane = tid & 31;
    __shared__ __align__(16) float tq_s[DD];
    __shared__ __align__(16) float w_s[SS];
    __shared__ float red[16];
    __shared__ float bval;
    __shared__ __align__(16) float2 part2[2][256];

    // q assembly: sum NP split-K partials + ba, apply tanh
    {
        int off = b*DD + tid;
        float qv = ba[tid];
#pragma unroll
        for (int p = 0; p < NP; p++) qv += g_qp[p*BB*DD + off];
        tq_s[tid] = tanh_fast(qv);
    }
    __syncthreads();

    // this lane's 16 d-values: [lane*16, lane*16+16)
    float tqv[16], vav[16];
#pragma unroll
    for (int k = 0; k < 4; k++) {
        float4 a = *(const float4*)(tq_s + lane*16 + k*4);
        float4 c = *(const float4*)(va   + lane*16 + k*4);
        tqv[k*4+0]=a.x; tqv[k*4+1]=a.y; tqv[k*4+2]=a.z; tqv[k*4+3]=a.w;
        vav[k*4+0]=c.x; vav[k*4+1]=c.y; vav[k*4+2]=c.z; vav[k*4+3]=c.w;
    }
    const float vb = va_b[0];

    // pass 1: scores. warp per s, 16 warps stride S; Uk already tanh'ed (fp16)
#pragma unroll 1
    for (int s = warp; s < SS; s += 16) {
        const __half* u = g_Uk + ((size_t)b*SS + s)*DD + lane*16;
        uint4 A0 = *(const uint4*)u;
        uint4 A1 = *(const uint4*)(u + 8);
        const __half2* h0 = (const __half2*)&A0;
        const __half2* h1 = (const __half2*)&A1;
        float acc = 0.f;
#pragma unroll
        for (int j = 0; j < 4; j++) {
            float2 f = __half22float2(h0[j]);
            acc += attn_term(f.x, tqv[j*2+0], vav[j*2+0]);
            acc += attn_term(f.y, tqv[j*2+1], vav[j*2+1]);
        }
#pragma unroll
        for (int j = 0; j < 4; j++) {
            float2 f = __half22float2(h1[j]);
            acc += attn_term(f.x, tqv[8+j*2+0], vav[8+j*2+0]);
            acc += attn_term(f.y, tqv[8+j*2+1], vav[8+j*2+1]);
        }
#pragma unroll
        for (int o = 16; o > 0; o >>= 1) acc += __shfl_xor_sync(0xffffffffu, acc, o);
        if (lane == 0) w_s[s] = acc + vb;
    }
    __syncthreads();

    // softmax over S (one thread per s)
    float sc = w_s[tid];
    float m = sc;
#pragma unroll
    for (int o = 16; o > 0; o >>= 1) m = fmaxf(m, __shfl_xor_sync(0xffffffffu, m, o));
    if (lane == 0) red[warp] = m;
    __syncthreads();
    if (tid == 0) {
        float mm = red[0];
#pragma unroll
        for (int i = 1; i < 16; i++) mm = fmaxf(mm, red[i]);
        bval = mm;
    }
    __syncthreads();
    float ex = __expf(sc - bval);
    float sm = ex;
#pragma unroll
    for (int o = 16; o > 0; o >>= 1) sm += __shfl_xor_sync(0xffffffffu, sm, o);
    if (lane == 0) red[warp] = sm;
    __syncthreads();
    if (tid == 0) {
        float tt = 0.f;
#pragma unroll
        for (int i = 0; i < 16; i++) tt += red[i];
        bval = tt;
    }
    __syncthreads();
    float wv = __fdividef(ex, bval);
    w_s[tid] = wv;
    out[(size_t)(BB*TT*OUTD + BB*DD) + ((size_t)b*TT + t)*SS + tid] = wv;
    __syncthreads();

    // pass 2: ctx. 2 groups of 256 threads; group g covers s in [g*256, g*256+256)
    {
        const int g = tid >> 8, l = tid & 255;
        const __half2* ep = (const __half2*)(g_e16 + ((size_t)b*SS + g*256)*DD) + l;
        float2 acc0 = make_float2(0.f, 0.f), acc1 = make_float2(0.f, 0.f);
#pragma unroll 4
        for (int s = 0; s < 256; s += 2) {
            float w0 = w_s[g*256 + s], w1 = w_s[g*256 + s + 1];
            float2 f0 = __half22float2(ep[(size_t)s * 256]);
            float2 f1 = __half22float2(ep[(size_t)(s+1) * 256]);
            acc0.x = fmaf(w0, f0.x, acc0.x);
            acc0.y = fmaf(w0, f0.y, acc0.y);
            acc1.x = fmaf(w1, f1.x, acc1.x);
            acc1.y = fmaf(w1, f1.y, acc1.y);
        }
        part2[g][l] = make_float2(acc0.x + acc1.x, acc0.y + acc1.y);
    }
    __syncthreads();
    if (tid < 256) {
        float2 a = part2[0][tid], c = part2[1][tid];
        ((float2*)(g_ctx + b*DD))[tid] = make_float2(a.x + c.x, a.y + c.y);
    }
}

// ---------------- GRU pointwise + x-term + output projection --------------
__global__ __launch_bounds__(512) void point_kernel(const float* __restrict__ b_ih,
                                                    const float* __restrict__ b_hh,
                                                    const float* __restrict__ W_out,
                                                    const float* __restrict__ b_out,
                                                    const float* __restrict__ target,
                                                    float* __restrict__ out, int t) {
    const int b = blockIdx.x, d = threadIdx.x;
    const int base = b*DD + d;

    float ir = b_ih[d], iz = b_ih[DD+d], in_ = b_ih[2*DD+d];
    float hr = b_hh[d], hz = b_hh[DD+d], hn  = b_hh[2*DD+d];
#pragma unroll
    for (int p = 0; p < NP; p++) {
        size_t o = ((size_t)p*BB + b)*GG;
        ir += g_gip[o + d]; iz += g_gip[o + DD + d]; in_ += g_gip[o + 2*DD + d];
        hr += g_ghp[o + d]; hz += g_ghp[o + DD + d]; hn  += g_ghp[o + 2*DD + d];
    }
    // teacher-forced x contribution (rank-3)
    float x0 = 0.f, x1 = 0.f, x2 = 0.f;
    if (t > 0) {
        const float* xp = target + ((size_t)b*TT + (t-1))*OUTD;
        x0 = xp[0]; x1 = xp[1]; x2 = xp[2];
    }
    ir  += x0*g_Wx[d]        + x1*g_Wx[GG + d]        + x2*g_Wx[2*GG + d];
    iz  += x0*g_Wx[DD+d]     + x1*g_Wx[GG + DD+d]     + x2*g_Wx[2*GG + DD+d];
    in_ += x0*g_Wx[2*DD+d]   + x1*g_Wx[GG + 2*DD+d]   + x2*g_Wx[2*GG + 2*DD+d];

    float r = sigmoid_fast(ir + hr);
    float z = sigmoid_fast(iz + hz);
    float n = tanh_fast(in_ + r*hn);
    float hp = g_h[base];
    float hnew = (1.f - z)*n + z*hp;
    g_h[base] = hnew;
    if (t == TT-1) out[BB*TT*OUTD + base] = hnew;   // hT region

    // out = h_new @ W_out^T + b_out
    float p0 = hnew*W_out[d], p1 = hnew*W_out[DD+d], p2 = hnew*W_out[2*DD+d];
#pragma unroll
    for (int o = 16; o > 0; o >>= 1) {
        p0 += __shfl_xor_sync(0xffffffffu, p0, o);
        p1 += __shfl_xor_sync(0xffffffffu, p1, o);
        p2 += __shfl_xor_sync(0xffffffffu, p2, o);
    }
    __shared__ float r0[16], r1[16], r2[16];
    int warp = d >> 5, lane = d & 31;
    if (lane == 0) { r0[warp] = p0; r1[warp] = p1; r2[warp] = p2; }
    __syncthreads();
    if (d == 0) {
        float s0=0.f, s1=0.f, s2=0.f;
#pragma unroll
        for (int i = 0; i < 16; i++) { s0 += r0[i]; s1 += r1[i]; s2 += r2[i]; }
        size_t ob = ((size_t)b*TT + t)*OUTD;
        out[ob+0] = s0 + b_out[0];
        out[ob+1] = s1 + b_out[1];
        out[ob+2] = s2 + b_out[2];
    }
}

// ---------------- host launcher -------------------------------------------
extern "C" void kernel_launch(void* const* d_in, const int* in_sizes, int n_in,
                              void* d_out, int out_size) {
    (void)in_sizes; (void)n_in; (void)out_size;
    const float* e_all  = (const float*)d_in[0];
    const float* e_last = (const float*)d_in[1];
    const float* target = (const float*)d_in[2];
    const float* Wa     = (const float*)d_in[3];
    const float* ba     = (const float*)d_in[4];
    const float* Ua     = (const float*)d_in[5];
    const float* bu     = (const float*)d_in[6];
    const float* Va_w   = (const float*)d_in[7];
    const float* Va_b   = (const float*)d_in[8];
    const float* W_ih   = (const float*)d_in[9];
    const float* b_ih   = (const float*)d_in[10];
    const float* W_hh   = (const float*)d_in[11];
    const float* b_hh   = (const float*)d_in[12];
    const float* W_out  = (const float*)d_in[13];
    const float* b_out  = (const float*)d_in[14];
    float* out = (float*)d_out;

    prep_kernel<<<(GG*DD + BB*DD + 3*GG + 255)/256, 256>>>(W_ih, e_last);
    cvt_kernel<<<(BB*SS*DD/4)/1024, 1024>>>(e_all);
    uk_gemm<<<dim3(8, 512), 256>>>(e_all, Ua, bu);

    for (int t = 0; t < TT; t++) {
        sk_gemm<0><<<dim3(32, 8), 256>>>(Wa, W_hh);                    // q + gh partials
        attn_kernel<<<BB, 512>>>(ba, Va_w, Va_b, out, t);              // w, ctx
        sk_gemm<1><<<dim3(24, 8), 256>>>(Wa, W_hh);                    // gi partials
        point_kernel<<<BB, 512>>>(b_ih, b_hh, W_out, b_out, target, out, t);
    }
}

// round 14
// speedup vs baseline: 1.2773x; 1.0218x over previous
#include <cuda_runtime.h>
#include <cuda_fp16.h>
#include <math.h>

#define BB   128
#define SS   512
#define DD   512
#define TT   64
#define OUTD 3
#define GG   (3*DD)        // 1536
#define NP   8             // split-K parts

typedef unsigned long long u64;

// ---------------- scratch (device globals: allocation-free) ----------------
__device__ __half g_Uk [(size_t)BB*SS*DD];  // tanh(Ua(keys)+bu), fp16
__device__ __half g_e16[(size_t)BB*SS*DD];  // fp16 copy of e_all
__device__ float g_h   [BB*DD];             // decoder hidden state
__device__ float g_ctx [BB*DD];             // attention context
__device__ float g_qp  [NP*BB*DD];          // split-K partials of q
__device__ float g_gip [NP*BB*GG];          // split-K partials of gi
__device__ float g_ghp [NP*BB*GG];          // split-K partials of gh
__device__ float g_W512[GG*DD];             // W_ih[:, :512] packed (aligned)
__device__ float g_Wx  [3*GG];              // W_ih[:, 512+j] packed [j][n]

// transcendentals (outside the hot loop)
__device__ __forceinline__ float tanh_fast(float x) {
    return 1.f - __fdividef(2.f, __expf(2.f*x) + 1.f);
}
__device__ __forceinline__ float sigmoid_fast(float x) {
    return __fdividef(1.f, 1.f + __expf(-x));
}

// ---- packed fp32x2 FMA helpers ----
__device__ __forceinline__ u64 bcast2(float x) {
    u64 d; asm("mov.b64 %0, {%1, %1};" : "=l"(d) : "f"(x)); return d;
}
__device__ __forceinline__ void ffma2(u64& acc, u64 a, u64 b) {
    asm("fma.rn.f32x2 %0, %1, %2, %0;" : "+l"(acc) : "l"(a), "l"(b));
}
__device__ __forceinline__ float2 unpack2(u64 v) {
    float2 f; asm("mov.b64 {%0, %1}, %2;" : "=f"(f.x), "=f"(f.y) : "l"(v)); return f;
}

// MUFU-free reciprocal for y in (0,2]: bit-hack seed + 2 Newton steps
__device__ __forceinline__ float rcp_fma(float y) {
    float r = __uint_as_float(0x7EF311C3u - __float_as_uint(y));
    r = r * fmaf(-y, r, 2.0f);
    r = r * fmaf(-y, r, 2.0f);
    return r;
}

// va * tanh(q+u) via tanh addition formula; tu=tanh(u), tq=tanh(q). No MUFU.
__device__ __forceinline__ float attn_term(float tu, float tq, float va) {
    float y = fmaf(tq, tu, 1.0f);
    return va * ((tq + tu) * rcp_fma(y));
}

// ---------------- prep: h0 = e_last; pack W_ih ----------------------------
__global__ void prep_kernel(const float* __restrict__ W_ih,
                            const float* __restrict__ e_last) {
    int i = blockIdx.x * blockDim.x + threadIdx.x;
    if (i < GG*DD) {
        int n = i >> 9, k = i & 511;
        g_W512[i] = W_ih[(size_t)n*515 + k];
    }
    int j = i - GG*DD;
    if (j >= 0 && j < BB*DD) g_h[j] = e_last[j];
    int m = i - GG*DD - BB*DD;
    if (m >= 0 && m < 3*GG) {
        int jj = m / GG, n = m % GG;
        g_Wx[m] = W_ih[(size_t)n*515 + 512 + jj];
    }
}

// ---------------- cvt: e16 = fp16(e_all) -----------------------------------
__global__ void cvt_kernel(const float* __restrict__ e_all) {
    size_t i = (size_t)blockIdx.x * blockDim.x + threadIdx.x;   // float4 index
    float4 v = ((const float4*)e_all)[i];
    __half2* o = (__half2*)g_e16 + i*2;
    o[0] = __floats2half2_rn(v.x, v.y);
    o[1] = __floats2half2_rn(v.z, v.w);
}

// ---------------- Uk GEMM -> tanh -> fp16 ---------------------------------
// M=65536, N=512, K=512. BM=128, BN=64, BK=16, 256 threads, f32x2 accum.
__global__ __launch_bounds__(256) void uk_gemm(const float* __restrict__ A,
                                               const float* __restrict__ W,
                                               const float* __restrict__ bias) {
    __shared__ __align__(16) float Xs[16][128];
    __shared__ __align__(16) float Ws[16][64];
    const int tid = threadIdx.x;
    const int tx = tid & 15, ty = tid >> 4;
    const int row0 = blockIdx.y * 128;
    const int n0   = blockIdx.x * 64;

    u64 acc2[4][4];
#pragma unroll
    for (int i = 0; i < 4; i++)
#pragma unroll
        for (int j = 0; j < 4; j++) acc2[i][j] = 0ull;

    for (int kc = 0; kc < 512; kc += 16) {
#pragma unroll
        for (int i = 0; i < 2; i++) {
            int l4 = tid*2 + i;
            int r = l4 >> 2, kq = (l4 & 3) << 2;
            float4 v = *(const float4*)(A + (size_t)(row0 + r)*512 + kc + kq);
            Xs[kq+0][r] = v.x; Xs[kq+1][r] = v.y; Xs[kq+2][r] = v.z; Xs[kq+3][r] = v.w;
        }
        {
            int n = tid >> 2, kq = (tid & 3) << 2;
            float4 v = *(const float4*)(W + (size_t)(n0 + n)*512 + kc + kq);
            Ws[kq+0][n] = v.x; Ws[kq+1][n] = v.y; Ws[kq+2][n] = v.z; Ws[kq+3][n] = v.w;
        }
        __syncthreads();
#pragma unroll
        for (int kk = 0; kk < 16; kk++) {
            const u64* ap = (const u64*)&Xs[kk][ty*8];
            u64 a2[4], b2[4];
#pragma unroll
            for (int i = 0; i < 4; i++) a2[i] = ap[i];
#pragma unroll
            for (int j = 0; j < 4; j++) b2[j] = bcast2(Ws[kk][tx*4 + j]);
#pragma unroll
            for (int i = 0; i < 4; i++)
#pragma unroll
                for (int j = 0; j < 4; j++) ffma2(acc2[i][j], a2[i], b2[j]);
        }
        __syncthreads();
    }
#pragma unroll
    for (int i = 0; i < 4; i++) {
        size_t r0r = (size_t)(row0 + ty*8 + 2*i);
#pragma unroll
        for (int j = 0; j < 4; j++) {
            int n = n0 + tx*4 + j;
            float2 v = unpack2(acc2[i][j]);
            g_Uk[r0r*512 + n]     = __float2half_rn(tanh_fast(v.x + bias[n]));
            g_Uk[(r0r+1)*512 + n] = __float2half_rn(tanh_fast(v.y + bias[n]));
        }
    }
}

// ---------------- skinny GEMM, K=512, split-K=8, double-buffered ----------
// WHICH==0: bx<8 -> q (X=g_h, W=Wa, N=512); bx>=8 -> gh (X=g_h, W=Whh, N=1536)
// WHICH==1: gi (X=g_ctx, W=g_W512, N=1536)
template<int WHICH>
__global__ __launch_bounds__(256) void sk_gemm(const float* __restrict__ Wq,
                                               const float* __restrict__ Whh) {
    __shared__ __align__(16) float Xs[2][16][128];
    __shared__ __align__(16) float Ws[2][16][64];
    const int tid = threadIdx.x;
    const int tx = tid & 15, ty = tid >> 4;
    const int bx = blockIdx.x;
    const int part = blockIdx.y;
    const float *X, *W; float* Cp; int n0, N;
    if (WHICH == 0) {
        if (bx < 8) { X = g_h; W = Wq;  Cp = g_qp;  n0 = bx*64;     N = 512;  }
        else        { X = g_h; W = Whh; Cp = g_ghp; n0 = (bx-8)*64; N = 1536; }
    } else          { X = g_ctx; W = g_W512; Cp = g_gip; n0 = bx*64; N = 1536; }
    const int kb = part * 64;

    // per-thread load coordinates
    const int xr0 = (tid*2) >> 2,       xk0 = ((tid*2) & 3) << 2;
    const int xr1 = (tid*2+1) >> 2,     xk1 = ((tid*2+1) & 3) << 2;
    const int wn  = tid >> 2,           wk  = (tid & 3) << 2;

    u64 acc2[4][4];
#pragma unroll
    for (int i = 0; i < 4; i++)
#pragma unroll
        for (int j = 0; j < 4; j++) acc2[i][j] = 0ull;

    // prologue: load chunk 0 into buffer 0
    {
        float4 v0 = *(const float4*)(X + (size_t)xr0*512 + kb + xk0);
        float4 v1 = *(const float4*)(X + (size_t)xr1*512 + kb + xk1);
        float4 wv = *(const float4*)(W + (size_t)(n0 + wn)*512 + kb + wk);
        Xs[0][xk0+0][xr0] = v0.x; Xs[0][xk0+1][xr0] = v0.y;
        Xs[0][xk0+2][xr0] = v0.z; Xs[0][xk0+3][xr0] = v0.w;
        Xs[0][xk1+0][xr1] = v1.x; Xs[0][xk1+1][xr1] = v1.y;
        Xs[0][xk1+2][xr1] = v1.z; Xs[0][xk1+3][xr1] = v1.w;
        Ws[0][wk+0][wn] = wv.x; Ws[0][wk+1][wn] = wv.y;
        Ws[0][wk+2][wn] = wv.z; Ws[0][wk+3][wn] = wv.w;
    }
    __syncthreads();

#pragma unroll
    for (int it = 0; it < 4; it++) {
        const int cur = it & 1, nxt = cur ^ 1;
        float4 v0, v1, wv;
        if (it < 3) {
            int kc = kb + (it+1)*16;
            v0 = *(const float4*)(X + (size_t)xr0*512 + kc + xk0);
            v1 = *(const float4*)(X + (size_t)xr1*512 + kc + xk1);
            wv = *(const float4*)(W + (size_t)(n0 + wn)*512 + kc + wk);
        }
#pragma unroll
        for (int kk = 0; kk < 16; kk++) {
            const u64* ap = (const u64*)&Xs[cur][kk][ty*8];
            u64 a2[4], b2[4];
#pragma unroll
            for (int i = 0; i < 4; i++) a2[i] = ap[i];
#pragma unroll
            for (int j = 0; j < 4; j++) b2[j] = bcast2(Ws[cur][kk][tx*4 + j]);
#pragma unroll
            for (int i = 0; i < 4; i++)
#pragma unroll
                for (int j = 0; j < 4; j++) ffma2(acc2[i][j], a2[i], b2[j]);
        }
        if (it < 3) {
            Xs[nxt][xk0+0][xr0] = v0.x; Xs[nxt][xk0+1][xr0] = v0.y;
            Xs[nxt][xk0+2][xr0] = v0.z; Xs[nxt][xk0+3][xr0] = v0.w;
            Xs[nxt][xk1+0][xr1] = v1.x; Xs[nxt][xk1+1][xr1] = v1.y;
            Xs[nxt][xk1+2][xr1] = v1.z; Xs[nxt][xk1+3][xr1] = v1.w;
            Ws[nxt][wk+0][wn] = wv.x; Ws[nxt][wk+1][wn] = wv.y;
            Ws[nxt][wk+2][wn] = wv.z; Ws[nxt][wk+3][wn] = wv.w;
            __syncthreads();
        }
    }
#pragma unroll
    for (int i = 0; i < 4; i++) {
        int b0 = ty*8 + 2*i;
        size_t base0 = ((size_t)part*BB + b0)     * (size_t)N + n0;
        size_t base1 = ((size_t)part*BB + b0 + 1) * (size_t)N + n0;
#pragma unroll
        for (int j = 0; j < 4; j++) {
            float2 v = unpack2(acc2[i][j]);
            Cp[base0 + tx*4 + j] = v.x;
            Cp[base1 + tx*4 + j] = v.y;
        }
    }
}

// score for one row: 16 fp16 tanh(u) values vs registers
__device__ __forceinline__ float score16(const __half* u, const float* tqv,
                                         const float* vav) {
    uint4 A0 = *(const uint4*)u;
    uint4 A1 = *(const uint4*)(u + 8);
    const __half2* h0 = (const __half2*)&A0;
    const __half2* h1 = (const __half2*)&A1;
    float acc = 0.f;
#pragma unroll
    for (int j = 0; j < 4; j++) {
        float2 f = __half22float2(h0[j]);
        acc += attn_term(f.x, tqv[j*2+0], vav[j*2+0]);
        acc += attn_term(f.y, tqv[j*2+1], vav[j*2+1]);
    }
#pragma unroll
    for (int j = 0; j < 4; j++) {
        float2 f = __half22float2(h1[j]);
        acc += attn_term(f.x, tqv[8+j*2+0], vav[8+j*2+0]);
        acc += attn_term(f.y, tqv[8+j*2+1], vav[8+j*2+1]);
    }
    return acc;
}

// ---------------- attention (512 threads, one block per b) ----------------
__global__ __launch_bounds__(512) void attn_kernel(const float* __restrict__ ba,
                                                   const float* __restrict__ va,
                                                   const float* __restrict__ va_b,
                                                   float* __restrict__ out, int t) {
    const int b = blockIdx.x;
    const int tid = threadIdx.x;
    const int warp = tid >> 5, lane = tid & 31;
    __shared__ __align__(16) float tq_s[DD];
    __shared__ __align__(16) float w_s[SS];
    __shared__ float red[16];
    __shared__ float bval;
    __shared__ __align__(16) float2 part2[2][256];

    // q assembly: sum NP split-K partials + ba, apply tanh
    {
        int off = b*DD + tid;
        float qv = ba[tid];
#pragma unroll
        for (int p = 0; p < NP; p++) qv += g_qp[p*BB*DD + off];
        tq_s[tid] = tanh_fast(qv);
    }
    __syncthreads();

    // this lane's 16 d-values: [lane*16, lane*16+16)
    float tqv[16], vav[16];
#pragma unroll
    for (int k = 0; k < 4; k++) {
        float4 a = *(const float4*)(tq_s + lane*16 + k*4);
        float4 c = *(const float4*)(va   + lane*16 + k*4);
        tqv[k*4+0]=a.x; tqv[k*4+1]=a.y; tqv[k*4+2]=a.z; tqv[k*4+3]=a.w;
        vav[k*4+0]=c.x; vav[k*4+1]=c.y; vav[k*4+2]=c.z; vav[k*4+3]=c.w;
    }
    const float vb = va_b[0];

    // pass 1: scores. warp handles rows s and s+256 per iteration (4 LDG.128
    // in flight/warp); Uk already tanh'ed (fp16)
#pragma unroll 2
    for (int i = 0; i < 16; i++) {
        const int s = warp + i*16;
        const __half* u0 = g_Uk + ((size_t)b*SS + s)*DD + lane*16;
        const __half* u1 = u0 + (size_t)256*DD;
        float acc_a = score16(u0, tqv, vav);
        float acc_b = score16(u1, tqv, vav);
#pragma unroll
        for (int o = 16; o > 0; o >>= 1) {
            acc_a += __shfl_xor_sync(0xffffffffu, acc_a, o);
            acc_b += __shfl_xor_sync(0xffffffffu, acc_b, o);
        }
        if (lane == 0) { w_s[s] = acc_a + vb; w_s[s+256] = acc_b + vb; }
    }
    __syncthreads();

    // softmax over S (one thread per s)
    float sc = w_s[tid];
    float m = sc;
#pragma unroll
    for (int o = 16; o > 0; o >>= 1) m = fmaxf(m, __shfl_xor_sync(0xffffffffu, m, o));
    if (lane == 0) red[warp] = m;
    __syncthreads();
    if (tid == 0) {
        float mm = red[0];
#pragma unroll
        for (int i = 1; i < 16; i++) mm = fmaxf(mm, red[i]);
        bval = mm;
    }
    __syncthreads();
    float ex = __expf(sc - bval);
    float sm = ex;
#pragma unroll
    for (int o = 16; o > 0; o >>= 1) sm += __shfl_xor_sync(0xffffffffu, sm, o);
    if (lane == 0) red[warp] = sm;
    __syncthreads();
    if (tid == 0) {
        float tt = 0.f;
#pragma unroll
        for (int i = 0; i < 16; i++) tt += red[i];
        bval = tt;
    }
    __syncthreads();
    float wv = __fdividef(ex, bval);
    w_s[tid] = wv;
    out[(size_t)(BB*TT*OUTD + BB*DD) + ((size_t)b*TT + t)*SS + tid] = wv;
    __syncthreads();

    // pass 2: ctx. 2 groups of 256 threads; group g covers s in [g*256, g*256+256)
    {
        const int g = tid >> 8, l = tid & 255;
        const __half2* ep = (const __half2*)(g_e16 + ((size_t)b*SS + g*256)*DD) + l;
        float2 acc0 = make_float2(0.f, 0.f), acc1 = make_float2(0.f, 0.f);
#pragma unroll 4
        for (int s = 0; s < 256; s += 2) {
            float w0 = w_s[g*256 + s], w1 = w_s[g*256 + s + 1];
            float2 f0 = __half22float2(ep[(size_t)s * 256]);
            float2 f1 = __half22float2(ep[(size_t)(s+1) * 256]);
            acc0.x = fmaf(w0, f0.x, acc0.x);
            acc0.y = fmaf(w0, f0.y, acc0.y);
            acc1.x = fmaf(w1, f1.x, acc1.x);
            acc1.y = fmaf(w1, f1.y, acc1.y);
        }
        part2[g][l] = make_float2(acc0.x + acc1.x, acc0.y + acc1.y);
    }
    __syncthreads();
    if (tid < 256) {
        float2 a = part2[0][tid], c = part2[1][tid];
        ((float2*)(g_ctx + b*DD))[tid] = make_float2(a.x + c.x, a.y + c.y);
    }
}

// ---------------- GRU pointwise + x-term + output projection --------------
__global__ __launch_bounds__(512) void point_kernel(const float* __restrict__ b_ih,
                                                    const float* __restrict__ b_hh,
                                                    const float* __restrict__ W_out,
                                                    const float* __restrict__ b_out,
                                                    const float* __restrict__ target,
                                                    float* __restrict__ out, int t) {
    const int b = blockIdx.x, d = threadIdx.x;
    const int base = b*DD + d;

    float ir = b_ih[d], iz = b_ih[DD+d], in_ = b_ih[2*DD+d];
    float hr = b_hh[d], hz = b_hh[DD+d], hn  = b_hh[2*DD+d];
#pragma unroll
    for (int p = 0; p < NP; p++) {
        size_t o = ((size_t)p*BB + b)*GG;
        ir += g_gip[o + d]; iz += g_gip[o + DD + d]; in_ += g_gip[o + 2*DD + d];
        hr += g_ghp[o + d]; hz += g_ghp[o + DD + d]; hn  += g_ghp[o + 2*DD + d];
    }
    // teacher-forced x contribution (rank-3)
    float x0 = 0.f, x1 = 0.f, x2 = 0.f;
    if (t > 0) {
        const float* xp = target + ((size_t)b*TT + (t-1))*OUTD;
        x0 = xp[0]; x1 = xp[1]; x2 = xp[2];
    }
    ir  += x0*g_Wx[d]        + x1*g_Wx[GG + d]        + x2*g_Wx[2*GG + d];
    iz  += x0*g_Wx[DD+d]     + x1*g_Wx[GG + DD+d]     + x2*g_Wx[2*GG + DD+d];
    in_ += x0*g_Wx[2*DD+d]   + x1*g_Wx[GG + 2*DD+d]   + x2*g_Wx[2*GG + 2*DD+d];

    float r = sigmoid_fast(ir + hr);
    float z = sigmoid_fast(iz + hz);
    float n = tanh_fast(in_ + r*hn);
    float hp = g_h[base];
    float hnew = (1.f - z)*n + z*hp;
    g_h[base] = hnew;
    if (t == TT-1) out[BB*TT*OUTD + base] = hnew;   // hT region

    // out = h_new @ W_out^T + b_out
    float p0 = hnew*W_out[d], p1 = hnew*W_out[DD+d], p2 = hnew*W_out[2*DD+d];
#pragma unroll
    for (int o = 16; o > 0; o >>= 1) {
        p0 += __shfl_xor_sync(0xffffffffu, p0, o);
        p1 += __shfl_xor_sync(0xffffffffu, p1, o);
        p2 += __shfl_xor_sync(0xffffffffu, p2, o);
    }
    __shared__ float r0[16], r1[16], r2[16];
    int warp = d >> 5, lane = d & 31;
    if (lane == 0) { r0[warp] = p0; r1[warp] = p1; r2[warp] = p2; }
    __syncthreads();
    if (d == 0) {
        float s0=0.f, s1=0.f, s2=0.f;
#pragma unroll
        for (int i = 0; i < 16; i++) { s0 += r0[i]; s1 += r1[i]; s2 += r2[i]; }
        size_t ob = ((size_t)b*TT + t)*OUTD;
        out[ob+0] = s0 + b_out[0];
        out[ob+1] = s1 + b_out[1];
        out[ob+2] = s2 + b_out[2];
    }
}

// ---------------- host launcher -------------------------------------------
extern "C" void kernel_launch(void* const* d_in, const int* in_sizes, int n_in,
                              void* d_out, int out_size) {
    (void)in_sizes; (void)n_in; (void)out_size;
    const float* e_all  = (const float*)d_in[0];
    const float* e_last = (const float*)d_in[1];
    const float* target = (const float*)d_in[2];
    const float* Wa     = (const float*)d_in[3];
    const float* ba     = (const float*)d_in[4];
    const float* Ua     = (const float*)d_in[5];
    const float* bu     = (const float*)d_in[6];
    const float* Va_w   = (const float*)d_in[7];
    const float* Va_b   = (const float*)d_in[8];
    const float* W_ih   = (const float*)d_in[9];
    const float* b_ih   = (const float*)d_in[10];
    const float* W_hh   = (const float*)d_in[11];
    const float* b_hh   = (const float*)d_in[12];
    const float* W_out  = (const float*)d_in[13];
    const float* b_out  = (const float*)d_in[14];
    float* out = (float*)d_out;

    prep_kernel<<<(GG*DD + BB*DD + 3*GG + 255)/256, 256>>>(W_ih, e_last);
    cvt_kernel<<<(BB*SS*DD/4)/1024, 1024>>>(e_all);
    uk_gemm<<<dim3(8, 512), 256>>>(e_all, Ua, bu);

    for (int t = 0; t < TT; t++) {
        sk_gemm<0><<<dim3(32, 8), 256>>>(Wa, W_hh);                    // q + gh partials
        attn_kernel<<<BB, 512>>>(ba, Va_w, Va_b, out, t);              // w, ctx
        sk_gemm<1><<<dim3(24, 8), 256>>>(Wa, W_hh);                    // gi partials
        point_kernel<<<BB, 512>>>(b_ih, b_hh, W_out, b_out, target, out, t);
    }
}